// round 11
// baseline (speedup 1.0000x reference)
#include <cuda_runtime.h>
#include <cstdint>

#define G 1024
#define BATCH 4
#define ROWS 24
#define NCHUNK 43              // 42*24=1008 + tail 15 = 1023
#define NCOLCTA 11             // 11 CTAs * 3 warps = 33 strips * 31 quads = 1023 cols
#define NBLOCKS (NCOLCTA * NCHUNK * BATCH)   // 1892 (one wave @ 13 CTA/SM)
#define ROWFLOATS (G * 3)      // 3072 floats per grid row
#define X_FLOATS (BATCH * G * G * 3)

// E = 1023*1023 + 1022*1023 + 1023*1022 = 3,137,541 ; N = B*E
#define N_TOTAL 12550164.0

__device__ double g_acc = 0.0;
__device__ unsigned int g_done = 0;

struct V3 { float x, y, z; };

__device__ __forceinline__ V3 vsub(V3 a, V3 b) {
    V3 r; r.x = a.x - b.x; r.y = a.y - b.y; r.z = a.z - b.z; return r;
}
__device__ __forceinline__ V3 vcross(V3 a, V3 b) {
    V3 r;
    r.x = fmaf(a.y, b.z, -a.z * b.y);
    r.y = fmaf(a.z, b.x, -a.x * b.z);
    r.z = fmaf(a.x, b.y, -a.y * b.x);
    return r;
}
__device__ __forceinline__ float vdot(V3 a, V3 b) {
    return fmaf(a.x, b.x, fmaf(a.y, b.y, a.z * b.z));
}
__device__ __forceinline__ float rq(V3 a) {            // rsqrt(max(|a|^2, eps^2))
    return rsqrtf(fmaxf(vdot(a, a), 1e-16f));
}
__device__ __forceinline__ V3 vscale(V3 a, float s) {
    V3 r; r.x = a.x * s; r.y = a.y * s; r.z = a.z * s; return r;
}
__device__ __forceinline__ V3 shup(V3 v) {
    V3 r;
    r.x = __shfl_up_sync(0xFFFFFFFFu, v.x, 1);
    r.y = __shfl_up_sync(0xFFFFFFFFu, v.y, 1);
    r.z = __shfl_up_sync(0xFFFFFFFFu, v.z, 1);
    return r;
}

#define CP_COMMIT() asm volatile("cp.async.commit_group;\n" ::: "memory")
#define CP_WAIT2()  asm volatile("cp.async.wait_group 2;\n" ::: "memory")

__device__ __forceinline__ void cp16(uint32_t saddr, const float* gptr, bool pred) {
    if (pred)
        asm volatile("cp.async.cg.shared.global [%0], [%1], 16;\n"
                     :: "r"(saddr), "l"(gptr) : "memory");
}

__global__ void __launch_bounds__(96, 13)
nc_fused_kernel(const float* __restrict__ x, float* __restrict__ out,
                unsigned int nblocks) {
    // per-warp ring: 4 slots x 448B (416B used)
    __shared__ float4 smem4[3][4][28];

    const int lane = threadIdx.x & 31;
    const int wid  = threadIdx.x >> 5;

    const int bx      = blockIdx.x;
    const int cta_col = bx % NCOLCTA;
    const int rest    = bx / NCOLCTA;
    const int chunk   = rest % NCHUNK;
    const int bb      = rest / NCHUNK;

    const int sw = cta_col * 3 + wid;       // strip 0..32
    const int c  = sw * 31 + lane;          // quad column 0..1023
    const int r0 = chunk * ROWS;
    const int nrows = min(ROWS, (G - 1) - r0);

    const float m_dh = (lane < 31) ? 1.0f : 0.0f;               // c<=1022 guaranteed when lane<31
    const float m_v  = (lane >= 1 && c <= 1022) ? 1.0f : 0.0f;
    const int   roff = (c <= 1022) ? 3 : 0;                     // clamp col-1024 access

    // 16B-aligned copy window: vertices [31*sw .. 31*sw+33], 416 bytes
    const int as_bytes = (372 * sw) & ~15;
    const int mis4     = ((372 * sw) - as_bytes) >> 2;          // 0..3 words
    const int w        = 3 * lane + mis4;                       // own-vertex word index

    const float* __restrict__ bbase = x + (size_t)bb * (size_t)G * G * 3;
    const float* __restrict__ xend  = x + (size_t)X_FLOATS;

    float* buf[4];
    #pragma unroll
    for (int s = 0; s < 4; ++s) buf[s] = (float*)&smem4[wid][s][0];

    // ---- issue copy group g (row r0-1+g, clamped), slot g&3
    auto issue = [&](int g) {
        int rr = min(max(r0 - 1 + g, 0), G - 1);
        const float* src = bbase + (size_t)rr * ROWFLOATS + (as_bytes >> 2) + lane * 4;
        uint32_t sa = (uint32_t)__cvta_generic_to_shared(&smem4[wid][g & 3][lane]);
        cp16(sa, src, lane < 26 && (src + 4) <= xend);
        CP_COMMIT();
    };

    // prologue: rows r0-1, r0, r0+1, r0+2 in flight
    issue(0); issue(1); issue(2); issue(3);
    CP_WAIT2();                 // groups 0,1 (rows r0-1, r0) complete
    __syncwarp();

    V3 p00 = {buf[1][w],        buf[1][w + 1],        buf[1][w + 2]};
    V3 p01 = {buf[1][w + roff], buf[1][w + roff + 1], buf[1][w + roff + 2]};
    V3 u2p = {0.f, 0.f, 0.f};
    if (r0 > 0) {
        V3 pm = {buf[0][w], buf[0][w + 1], buf[0][w + 2]};
        V3 e2 = vsub(p00, pm);
        V3 dd = vsub(p01, pm);
        V3 cB = vcross(e2, dd);
        u2p = vscale(cB, rq(cB));
    }

    float sum = 0.0f;
    #pragma unroll 2
    for (int it = 0; it < nrows; ++it) {
        issue(it + 4);          // row r0+it+3 -> slot it&3 (last read at iter it-2)
        CP_WAIT2();             // group it+2 (row r0+it+1) complete
        __syncwarp();

        const float* bn = buf[(it + 2) & 3];
        V3 p10 = {bn[w],        bn[w + 1],        bn[w + 2]};
        V3 p11 = {bn[w + roff], bn[w + roff + 1], bn[w + roff + 2]};

        V3 e1 = vsub(p01, p00);
        V3 e2 = vsub(p10, p00);
        V3 dd = vsub(p11, p00);
        V3 cA = vcross(dd, e1);          // T1 normal
        V3 cB = vcross(e2, dd);          // T2 normal
        V3 u1 = vscale(cA, rq(cA));
        V3 u2 = vscale(cB, rq(cB));

        // diag + horiz (u2p==0 at global row 0 -> horiz contributes 0)
        sum = fmaf(m_dh, vdot(u1, u2) + vdot(u1, u2p), sum);
        // vertical: left quad's u1 via shuffle
        V3 u1l = shup(u1);
        sum = fmaf(m_v, vdot(u2, u1l), sum);

        u2p = u2; p00 = p10; p01 = p11;
    }

    // ---- block reduction (3 warps) ----
    #pragma unroll
    for (int off = 16; off > 0; off >>= 1)
        sum += __shfl_down_sync(0xFFFFFFFFu, sum, off);

    __shared__ float warp_sums[3];
    if (lane == 0) warp_sums[wid] = sum;
    __syncthreads();

    __shared__ bool is_last;
    if (wid == 0) {
        float sv = (lane < 3) ? warp_sums[lane] : 0.0f;
        #pragma unroll
        for (int off = 2; off > 0; off >>= 1)
            sv += __shfl_down_sync(0xFFFFFFFFu, sv, off);
        if (lane == 0) {
            atomicAdd(&g_acc, (double)sv);
            __threadfence();
            unsigned int done = atomicInc(&g_done, nblocks - 1);
            is_last = (done == nblocks - 1);
        }
    }
    __syncthreads();

    if (is_last && threadIdx.x == 0) {
        double acc = atomicAdd(&g_acc, 0.0);      // coherent read
        out[0] = (float)(1.0 - acc / N_TOTAL);    // loss = 1 - mean(cos)
        __threadfence();
        g_acc = 0.0;                               // g_done wrapped via atomicInc
    }
}

extern "C" void kernel_launch(void* const* d_in, const int* in_sizes, int n_in,
                              void* d_out, int out_size) {
    const float* x = (const float*)d_in[0];
    float* out = (float*)d_out;

    dim3 block(96, 1, 1);
    dim3 grid(NBLOCKS, 1, 1);   // 1892 CTAs -> one wave @ 13 CTA/SM
    nc_fused_kernel<<<grid, block>>>(x, out, NBLOCKS);
}

// round 12
// speedup vs baseline: 1.2153x; 1.2153x over previous
#include <cuda_runtime.h>

#define G 1024
#define BATCH 4
#define ROWS 17
#define NCHUNK 62              // 62*17=1054 >= 1023 (last chunks partial/empty)
#define NSTRIP 33              // 33 strips * 31 quads = 1023 columns
#define NPAIR 2                // batch pairs (0,1) and (2,3)
#define ROWSTRIDE (G * 3)
#define BSTRIDE (G * G * 3)
#define TOTWARPS (NSTRIP * NCHUNK * NPAIR)   // 4092
#define NBLOCKS (TOTWARPS / 4)               // 1023 blocks of 128 thr (one wave @7 CTA/SM)

// E = 1023*1023 + 1022*1023 + 1023*1022 = 3,137,541 ; N = B*E
#define N_TOTAL 12550164.0

__device__ double g_acc = 0.0;
__device__ unsigned int g_done = 0;

typedef unsigned long long ull;
struct P3 { ull x, y, z; };

__device__ __forceinline__ ull pk(float lo, float hi) {
    ull r; asm("mov.b64 %0, {%1, %2};" : "=l"(r) : "f"(lo), "f"(hi)); return r;
}
__device__ __forceinline__ void upk(float& lo, float& hi, ull v) {
    asm("mov.b64 {%0, %1}, %2;" : "=f"(lo), "=f"(hi) : "l"(v));
}
__device__ __forceinline__ ull f2mul(ull a, ull b) {
    ull r; asm("mul.rn.f32x2 %0, %1, %2;" : "=l"(r) : "l"(a), "l"(b)); return r;
}
__device__ __forceinline__ ull f2add(ull a, ull b) {
    ull r; asm("add.rn.f32x2 %0, %1, %2;" : "=l"(r) : "l"(a), "l"(b)); return r;
}
__device__ __forceinline__ ull f2sub(ull a, ull b) {
    ull r; asm("sub.rn.f32x2 %0, %1, %2;" : "=l"(r) : "l"(a), "l"(b)); return r;
}
__device__ __forceinline__ ull f2fma(ull a, ull b, ull c) {
    ull r; asm("fma.rn.f32x2 %0, %1, %2, %3;" : "=l"(r) : "l"(a), "l"(b), "l"(c)); return r;
}

__device__ __forceinline__ P3 sub3(P3 a, P3 b) {
    return P3{f2sub(a.x, b.x), f2sub(a.y, b.y), f2sub(a.z, b.z)};
}
__device__ __forceinline__ P3 cross3(P3 a, P3 b) {
    P3 r;
    r.x = f2sub(f2mul(a.y, b.z), f2mul(a.z, b.y));
    r.y = f2sub(f2mul(a.z, b.x), f2mul(a.x, b.z));
    r.z = f2sub(f2mul(a.x, b.y), f2mul(a.y, b.x));
    return r;
}
__device__ __forceinline__ ull dot3(P3 a, P3 b) {
    return f2fma(a.x, b.x, f2fma(a.y, b.y, f2mul(a.z, b.z)));
}
__device__ __forceinline__ P3 scale3(P3 a, ull s) {
    return P3{f2mul(a.x, s), f2mul(a.y, s), f2mul(a.z, s)};
}
__device__ __forceinline__ ull rq2(ull q) {     // per-half rsqrt(max(q,1e-16))
    float lo, hi; upk(lo, hi, q);
    lo = rsqrtf(fmaxf(lo, 1e-16f));
    hi = rsqrtf(fmaxf(hi, 1e-16f));
    return pk(lo, hi);
}
__device__ __forceinline__ ull shup2(ull v) {
    float lo, hi; upk(lo, hi, v);
    lo = __shfl_up_sync(0xFFFFFFFFu, lo, 1);
    hi = __shfl_up_sync(0xFFFFFFFFu, hi, 1);
    return pk(lo, hi);
}
__device__ __forceinline__ P3 shup3(P3 v) {
    return P3{shup2(v.x), shup2(v.y), shup2(v.z)};
}
// load one vertex from both batches of the pair, packed (lo=batchA, hi=batchB)
__device__ __forceinline__ P3 ldp(const float* __restrict__ pa, const float* __restrict__ pb) {
    return P3{pk(pa[0], pb[0]), pk(pa[1], pb[1]), pk(pa[2], pb[2])};
}

__global__ void __launch_bounds__(128, 7)
nc_fused_kernel(const float* __restrict__ x, float* __restrict__ out,
                unsigned int nblocks) {
    const int lane = threadIdx.x & 31;
    const int wid  = threadIdx.x >> 5;
    const int W    = blockIdx.x * 4 + wid;

    const int strip = W % NSTRIP;
    const int rest  = W / NSTRIP;
    const int chunk = rest % NCHUNK;
    const int bp    = rest / NCHUNK;          // batch pair 0 or 1

    const int c  = strip * 31 + lane;         // 0..1023 (all in-bounds)
    const int r0 = chunk * ROWS;
    const int nrows = min(ROWS, (G - 1) - r0);

    ull sump = 0;                              // packed accumulator (two batches)
    if (nrows > 0) {
        const int roff = (c <= 1022) ? 3 : 0;  // clamp col 1023's "+1" to itself (masked)
        const float mdh = (lane < 31) ? 1.0f : 0.0f;
        const float mv  = (lane >= 1 && c <= 1022) ? 1.0f : 0.0f;
        const ull mdhp = pk(mdh, mdh);
        const ull mvp  = pk(mv, mv);

        const float* __restrict__ rowA = x + (size_t)(2 * bp) * BSTRIDE + ((size_t)r0 * G + c) * 3;
        const float* __restrict__ rowB = rowA + BSTRIDE;

        P3 p00 = ldp(rowA, rowB);
        P3 p01 = ldp(rowA + roff, rowB + roff);
        P3 u2p = P3{0, 0, 0};
        if (r0 >= 1) {                          // u2 of quad (r0-1,c)
            P3 pm = ldp(rowA - ROWSTRIDE, rowB - ROWSTRIDE);
            P3 e2 = sub3(p00, pm);
            P3 dd = sub3(p01, pm);
            P3 cB = cross3(e2, dd);
            u2p = scale3(cB, rq2(dot3(cB, cB)));
        }

        #pragma unroll 2
        for (int it = 0; it < nrows; ++it) {
            const float* __restrict__ nrA = rowA + ROWSTRIDE;
            const float* __restrict__ nrB = rowB + ROWSTRIDE;
            P3 p10 = ldp(nrA, nrB);
            P3 p11 = ldp(nrA + roff, nrB + roff);

            P3 e1 = sub3(p01, p00);
            P3 e2 = sub3(p10, p00);
            P3 dd = sub3(p11, p00);

            P3 cA = cross3(dd, e1);            // T1 normal
            P3 cB = cross3(e2, dd);            // T2 normal
            P3 u1 = scale3(cA, rq2(dot3(cA, cA)));
            P3 u2 = scale3(cB, rq2(dot3(cB, cB)));

            // diag + horiz (u2p = 0 at global row 0 -> horiz contributes 0)
            ull dh = f2add(dot3(u1, u2), dot3(u1, u2p));
            sump = f2fma(mdhp, dh, sump);
            // vertical: left quad's u1 via shuffle
            P3 u1l = shup3(u1);
            sump = f2fma(mvp, dot3(u2, u1l), sump);

            u2p = u2; p00 = p10; p01 = p11;
            rowA = nrA; rowB = nrB;
        }
    }

    float slo, shi; upk(slo, shi, sump);
    float sum = slo + shi;

    // ---- block reduction (4 warps) ----
    #pragma unroll
    for (int off = 16; off > 0; off >>= 1)
        sum += __shfl_down_sync(0xFFFFFFFFu, sum, off);

    __shared__ float warp_sums[4];
    if (lane == 0) warp_sums[wid] = sum;
    __syncthreads();

    __shared__ bool is_last;
    if (wid == 0) {
        float sv = (lane < 4) ? warp_sums[lane] : 0.0f;
        #pragma unroll
        for (int off = 2; off > 0; off >>= 1)
            sv += __shfl_down_sync(0xFFFFFFFFu, sv, off);
        if (lane == 0) {
            atomicAdd(&g_acc, (double)sv);
            __threadfence();
            unsigned int done = atomicInc(&g_done, nblocks - 1);
            is_last = (done == nblocks - 1);
        }
    }
    __syncthreads();

    if (is_last && threadIdx.x == 0) {
        double acc = atomicAdd(&g_acc, 0.0);      // coherent read
        out[0] = (float)(1.0 - acc / N_TOTAL);    // loss = 1 - mean(cos)
        __threadfence();
        g_acc = 0.0;                               // g_done wrapped via atomicInc
    }
}

extern "C" void kernel_launch(void* const* d_in, const int* in_sizes, int n_in,
                              void* d_out, int out_size) {
    const float* x = (const float*)d_in[0];
    float* out = (float*)d_out;

    dim3 block(128, 1, 1);
    dim3 grid(NBLOCKS, 1, 1);   // 1023 blocks -> one wave @ 7 CTA/SM
    nc_fused_kernel<<<grid, block>>>(x, out, NBLOCKS);
}